// round 1
// baseline (speedup 1.0000x reference)
#include <cuda_runtime.h>
#include <math.h>

// Problem constants
#define Bb 2
#define Tt 2048
#define Dd 512
#define Hh 8

// ---------------- scratch (device globals; no allocations allowed) ----------------
__device__ __align__(16) float g_QZ[(size_t)Bb * Hh * Tt * Dd];   // 64 MB
__device__ __align__(16) float g_PZ[(size_t)Bb * Hh * Tt * Dd];   // 64 MB
__device__ __align__(16) float g_S [(size_t)Bb * Hh * Tt * Tt];   // 256 MB
__device__ __align__(16) float g_Y [(size_t)Bb * Tt * Dd];        // 8 MB
__device__ __align__(16) float g_Z [(size_t)Bb * Tt * Dd];        // 8 MB
__device__ __align__(16) float g_M1[(size_t)Bb * Tt * 2 * Dd];    // 16 MB
__device__ __align__(16) float g_Z2[(size_t)Bb * Tt * Dd];        // 8 MB

// ---------------- tiled SGEMM, C = alpha * A @ B^T (+epilogue) ----------------
// A: M x K row-major, B: N x K row-major, C: M x N row-major.
// 128x128 block tile, K-tile 8, 256 threads, 8x8 per-thread micro-tile.
constexpr int BM = 128, BN = 128, BK = 8, TM = 8, TN = 8, NTHR = 256;

template <bool CAUSAL, bool RELU>
__global__ __launch_bounds__(NTHR)
void sgemm_nt(const float* __restrict__ Aall, const float* __restrict__ Ball,
              float* __restrict__ Call,
              int M, int N, int K,
              int divA, int modA, size_t strideA,
              int divB, int modB, size_t strideB,
              size_t strideC,
              const float* __restrict__ bias,
              const float* __restrict__ residual,
              float alpha)
{
    const int z = blockIdx.z;
    const float* A  = Aall + (size_t)((z / divA) % modA) * strideA;
    const float* Bm = Ball + (size_t)((z / divB) % modB) * strideB;
    float* C = Call + (size_t)z * strideC;

    const int rowStart = blockIdx.y * BM;
    const int colStart = blockIdx.x * BN;

    if (CAUSAL) {
        // tile fully above the diagonal (colStart >= rowStart + BM) -> never read later
        if (colStart > rowStart) return;
    }

    __shared__ __align__(16) float As[BK][BM];
    __shared__ __align__(16) float Bs[BK][BN];

    const int tid  = threadIdx.x;
    const int aRow = tid >> 1;          // 0..127
    const int aCol = (tid & 1) << 2;    // 0 or 4
    const int ty   = tid >> 4;          // 0..15
    const int tx   = tid & 15;          // 0..15

    float acc[TM][TN];
#pragma unroll
    for (int i = 0; i < TM; i++)
#pragma unroll
        for (int j = 0; j < TN; j++) acc[i][j] = 0.0f;

    for (int k0 = 0; k0 < K; k0 += BK) {
        float4 a4 = *reinterpret_cast<const float4*>(&A[(size_t)(rowStart + aRow) * K + k0 + aCol]);
        As[aCol + 0][aRow] = a4.x;
        As[aCol + 1][aRow] = a4.y;
        As[aCol + 2][aRow] = a4.z;
        As[aCol + 3][aRow] = a4.w;
        float4 b4 = *reinterpret_cast<const float4*>(&Bm[(size_t)(colStart + aRow) * K + k0 + aCol]);
        Bs[aCol + 0][aRow] = b4.x;
        Bs[aCol + 1][aRow] = b4.y;
        Bs[aCol + 2][aRow] = b4.z;
        Bs[aCol + 3][aRow] = b4.w;
        __syncthreads();

#pragma unroll
        for (int kk = 0; kk < BK; kk++) {
            float aF[TM], bF[TN];
#pragma unroll
            for (int i = 0; i < TM; i++) aF[i] = As[kk][ty * TM + i];
#pragma unroll
            for (int j = 0; j < TN; j++) bF[j] = Bs[kk][tx * TN + j];
#pragma unroll
            for (int i = 0; i < TM; i++)
#pragma unroll
                for (int j = 0; j < TN; j++)
                    acc[i][j] = fmaf(aF[i], bF[j], acc[i][j]);
        }
        __syncthreads();
    }

    // epilogue
#pragma unroll
    for (int i = 0; i < TM; i++) {
        const int r  = rowStart + ty * TM + i;
        const int c0 = colStart + tx * TN;
        float v[TN];
#pragma unroll
        for (int j = 0; j < TN; j++) {
            float t = acc[i][j] * alpha;
            if (CAUSAL) { if (c0 + j > r) t = 0.0f; }
            if (bias)     t += bias[c0 + j];
            if (RELU)     t = fmaxf(t, 0.0f);
            if (residual) t += residual[(size_t)r * N + c0 + j];
            v[j] = t;
        }
        float4* dst = reinterpret_cast<float4*>(&C[(size_t)r * N + c0]);
        dst[0] = make_float4(v[0], v[1], v[2], v[3]);
        dst[1] = make_float4(v[4], v[5], v[6], v[7]);
    }
}

// ---------------- y GEMM: Y[b] = (1/H) * sum_h S[b,h] @ PZ[b,h] ----------------
// A = S (T x T row-major), B = PZ (T x D row-major, NN layout). Causal K-limit.
__global__ __launch_bounds__(NTHR)
void ygemm(const float* __restrict__ S, const float* __restrict__ PZ,
           float* __restrict__ Y)
{
    const int b = blockIdx.z;
    const int rowStart = blockIdx.y * BM;   // t
    const int colStart = blockIdx.x * BN;   // e (N = Dd = 512)

    __shared__ __align__(16) float As[BK][BM];
    __shared__ __align__(16) float Bs[BK][BN];

    const int tid  = threadIdx.x;
    const int aRow = tid >> 1;
    const int aCol = (tid & 1) << 2;
    const int bRow = tid >> 5;          // 0..7
    const int bCol = (tid & 31) << 2;   // 0..124
    const int ty   = tid >> 4;
    const int tx   = tid & 15;

    float acc[TM][TN];
#pragma unroll
    for (int i = 0; i < TM; i++)
#pragma unroll
        for (int j = 0; j < TN; j++) acc[i][j] = 0.0f;

    const int kmax = rowStart + BM;  // causal: only s < rowStart+128 contribute

    for (int h = 0; h < Hh; h++) {
        const float* Ah = S  + ((size_t)(b * Hh + h)) * Tt * Tt;
        const float* Bh = PZ + ((size_t)(b * Hh + h)) * Tt * Dd;
        for (int k0 = 0; k0 < kmax; k0 += BK) {
            float4 a4 = *reinterpret_cast<const float4*>(&Ah[(size_t)(rowStart + aRow) * Tt + k0 + aCol]);
            As[aCol + 0][aRow] = a4.x;
            As[aCol + 1][aRow] = a4.y;
            As[aCol + 2][aRow] = a4.z;
            As[aCol + 3][aRow] = a4.w;
            float4 b4 = *reinterpret_cast<const float4*>(&Bh[(size_t)(k0 + bRow) * Dd + colStart + bCol]);
            *reinterpret_cast<float4*>(&Bs[bRow][bCol]) = b4;
            __syncthreads();

#pragma unroll
            for (int kk = 0; kk < BK; kk++) {
                float aF[TM], bF[TN];
#pragma unroll
                for (int i = 0; i < TM; i++) aF[i] = As[kk][ty * TM + i];
#pragma unroll
                for (int j = 0; j < TN; j++) bF[j] = Bs[kk][tx * TN + j];
#pragma unroll
                for (int i = 0; i < TM; i++)
#pragma unroll
                    for (int j = 0; j < TN; j++)
                        acc[i][j] = fmaf(aF[i], bF[j], acc[i][j]);
            }
            __syncthreads();
        }
    }

    const float inv_h = 1.0f / (float)Hh;
    float* Yb = Y + (size_t)b * Tt * Dd;
#pragma unroll
    for (int i = 0; i < TM; i++) {
        const int r  = rowStart + ty * TM + i;
        const int c0 = colStart + tx * TN;
        float4* dst = reinterpret_cast<float4*>(&Yb[(size_t)r * Dd + c0]);
        dst[0] = make_float4(acc[i][0] * inv_h, acc[i][1] * inv_h, acc[i][2] * inv_h, acc[i][3] * inv_h);
        dst[1] = make_float4(acc[i][4] * inv_h, acc[i][5] * inv_h, acc[i][6] * inv_h, acc[i][7] * inv_h);
    }
}

// ---------------- fused residual + LayerNorm: Z = LN(Y + X) * gamma + beta ----------------
__global__ __launch_bounds__(128)
void ln_kernel(const float* __restrict__ Y, const float* __restrict__ X,
               const float* __restrict__ gamma, const float* __restrict__ beta,
               float* __restrict__ Z)
{
    const int row = blockIdx.x;             // 0 .. B*T-1
    const size_t off = (size_t)row * Dd;
    const int tid = threadIdx.x;            // 128 threads, 4 elems each

    float4 y4 = *reinterpret_cast<const float4*>(&Y[off + tid * 4]);
    float4 x4 = *reinterpret_cast<const float4*>(&X[off + tid * 4]);
    float v[4] = {y4.x + x4.x, y4.y + x4.y, y4.z + x4.z, y4.w + x4.w};

    float s  = v[0] + v[1] + v[2] + v[3];
    float sq = v[0] * v[0] + v[1] * v[1] + v[2] * v[2] + v[3] * v[3];

#pragma unroll
    for (int o = 16; o > 0; o >>= 1) {
        s  += __shfl_xor_sync(0xffffffffu, s, o);
        sq += __shfl_xor_sync(0xffffffffu, sq, o);
    }

    __shared__ float sh[8];
    __shared__ float s_mean, s_rstd;
    const int w = tid >> 5, lane = tid & 31;
    if (lane == 0) { sh[w] = s; sh[4 + w] = sq; }
    __syncthreads();
    if (tid == 0) {
        float ts = sh[0] + sh[1] + sh[2] + sh[3];
        float tq = sh[4] + sh[5] + sh[6] + sh[7];
        float mean = ts / (float)Dd;
        float var  = tq / (float)Dd - mean * mean;
        s_mean = mean;
        s_rstd = rsqrtf(var + 1e-5f);
    }
    __syncthreads();

    const float mean = s_mean, rstd = s_rstd;
#pragma unroll
    for (int i = 0; i < 4; i++) {
        const int c = tid * 4 + i;
        Z[off + c] = (v[i] - mean) * rstd * gamma[c] + beta[c];
    }
}

// ---------------- launcher ----------------
extern "C" void kernel_launch(void* const* d_in, const int* in_sizes, int n_in,
                              void* d_out, int out_size)
{
    (void)in_sizes; (void)n_in; (void)out_size;
    const float* x     = (const float*)d_in[0];
    const float* P     = (const float*)d_in[1];
    const float* Q     = (const float*)d_in[2];
    const float* gamma = (const float*)d_in[3];
    const float* beta  = (const float*)d_in[4];
    const float* W1    = (const float*)d_in[5];
    const float* b1    = (const float*)d_in[6];
    const float* W2    = (const float*)d_in[7];
    const float* b2    = (const float*)d_in[8];
    const float* Wp    = (const float*)d_in[9];
    const float* bp    = (const float*)d_in[10];
    float* out = (float*)d_out;

    float *QZ, *PZ, *S, *Y, *Z, *M1, *Z2;
    cudaGetSymbolAddress((void**)&QZ, g_QZ);
    cudaGetSymbolAddress((void**)&PZ, g_PZ);
    cudaGetSymbolAddress((void**)&S,  g_S);
    cudaGetSymbolAddress((void**)&Y,  g_Y);
    cudaGetSymbolAddress((void**)&Z,  g_Z);
    cudaGetSymbolAddress((void**)&M1, g_M1);
    cudaGetSymbolAddress((void**)&Z2, g_Z2);

    const dim3 blk(NTHR);
    const float inv_sqrt_d = 1.0f / sqrtf((float)Dd);

    // 1) QZ[b,h] = x[b] @ Q[h]^T   (z = b*H + h)
    sgemm_nt<false, false><<<dim3(Dd / BN, Tt / BM, Bb * Hh), blk>>>(
        x, Q, QZ, Tt, Dd, Dd,
        Hh, Bb, (size_t)Tt * Dd,      // A: x[b],  b = z / H
        1,  Hh, (size_t)Dd * Dd,      // B: Q[h],  h = z % H
        (size_t)Tt * Dd, nullptr, nullptr, 1.0f);

    // 2) PZ[b,h] = x[b] @ P[h]^T
    sgemm_nt<false, false><<<dim3(Dd / BN, Tt / BM, Bb * Hh), blk>>>(
        x, P, PZ, Tt, Dd, Dd,
        Hh, Bb, (size_t)Tt * Dd,
        1,  Hh, (size_t)Dd * Dd,
        (size_t)Tt * Dd, nullptr, nullptr, 1.0f);

    // 3) S[b,h] = tril(QZ[b,h] @ x[b]^T) / sqrt(D)
    sgemm_nt<true, false><<<dim3(Tt / BN, Tt / BM, Bb * Hh), blk>>>(
        QZ, x, S, Tt, Tt, Dd,
        1,  Bb * Hh, (size_t)Tt * Dd, // A: QZ[z]
        Hh, Bb,      (size_t)Tt * Dd, // B: x[b]
        (size_t)Tt * Tt, nullptr, nullptr, inv_sqrt_d);

    // 4) Y[b] = (1/H) * sum_h S[b,h] @ PZ[b,h]   (causal K-limit)
    ygemm<<<dim3(Dd / BN, Tt / BM, Bb), blk>>>(S, PZ, Y);

    // 5) Z = LayerNorm(Y + x) * gamma + beta
    ln_kernel<<<Bb * Tt, 128>>>(Y, x, gamma, beta, Z);

    // 6) M1 = relu(Z @ W1^T + b1)     [B*T, 2D]
    sgemm_nt<false, true><<<dim3(2 * Dd / BN, (Bb * Tt) / BM, 1), blk>>>(
        Z, W1, M1, Bb * Tt, 2 * Dd, Dd,
        1, 1, 0, 1, 1, 0, 0, b1, nullptr, 1.0f);

    // 7) Z2 = Z + (M1 @ W2^T + b2)    [B*T, D]
    sgemm_nt<false, false><<<dim3(Dd / BN, (Bb * Tt) / BM, 1), blk>>>(
        M1, W2, Z2, Bb * Tt, Dd, 2 * Dd,
        1, 1, 0, 1, 1, 0, 0, b2, Z, 1.0f);

    // 8) out = Z2 @ Wp^T + bp
    sgemm_nt<false, false><<<dim3(Dd / BN, (Bb * Tt) / BM, 1), blk>>>(
        Z2, Wp, out, Bb * Tt, Dd, Dd,
        1, 1, 0, 1, 1, 0, 0, bp, nullptr, 1.0f);
}

// round 3
// speedup vs baseline: 3.5164x; 3.5164x over previous
#include <cuda_runtime.h>
#include <cuda_bf16.h>
#include <stdint.h>
#include <math.h>

#define Bb 2
#define Tt 2048
#define Dd 512
#define Hh 8

// ---------------- scratch (device globals) ----------------
__device__ __align__(16) float g_QZ [(size_t)Bb*Hh*Tt*Dd];   // 64 MB
__device__ __align__(16) float g_PZ [(size_t)Bb*Hh*Tt*Dd];   // 64 MB
__device__ __align__(16) float g_S  [(size_t)Bb*Hh*Tt*Tt];   // 256 MB
__device__ __align__(16) float g_Yp [(size_t)Bb*Hh*Tt*Dd];   // 64 MB
__device__ __align__(16) float g_Z  [(size_t)Bb*Tt*Dd];      // 8 MB
__device__ __align__(16) float g_M1 [(size_t)Bb*Tt*2*Dd];    // 16 MB
__device__ __align__(16) float g_Z2 [(size_t)Bb*Tt*Dd];      // 8 MB

constexpr int BM = 128, BN = 128, BK = 32, NTHR = 256;

// smem tile geometry
constexpr int A_PITCH = 80;                 // 4 chunks of 16B + 16B pad -> ldmatrix conflict-free
constexpr int A_TILE  = BM * A_PITCH;       // 10240 B (bf16 128x32)
constexpr int BNT_PITCH = 80;
constexpr int BNT_TILE  = BN * BNT_PITCH;   // 10240
constexpr int BNN_PITCH = 272;              // 16 chunks of 16B + 16B pad
constexpr int BNN_TILE  = BK * BNN_PITCH;   // 8704

// ---------------- PTX helpers ----------------
__device__ __forceinline__ void ldsm_x4(uint32_t (&r)[4], uint32_t addr) {
    asm volatile("ldmatrix.sync.aligned.m8n8.x4.shared.b16 {%0,%1,%2,%3}, [%4];"
                 : "=r"(r[0]), "=r"(r[1]), "=r"(r[2]), "=r"(r[3]) : "r"(addr));
}
__device__ __forceinline__ void ldsm_x4_t(uint32_t (&r)[4], uint32_t addr) {
    asm volatile("ldmatrix.sync.aligned.m8n8.x4.trans.shared.b16 {%0,%1,%2,%3}, [%4];"
                 : "=r"(r[0]), "=r"(r[1]), "=r"(r[2]), "=r"(r[3]) : "r"(addr));
}
__device__ __forceinline__ void mma16816(float (&d)[4], const uint32_t (&a)[4],
                                         uint32_t b0, uint32_t b1) {
    asm volatile("mma.sync.aligned.m16n8k16.row.col.f32.bf16.bf16.f32 "
                 "{%0,%1,%2,%3}, {%4,%5,%6,%7}, {%8,%9}, {%0,%1,%2,%3};"
                 : "+f"(d[0]), "+f"(d[1]), "+f"(d[2]), "+f"(d[3])
                 : "r"(a[0]), "r"(a[1]), "r"(a[2]), "r"(a[3]), "r"(b0), "r"(b1));
}

// fp32 pair -> packed bf16x2 hi + bf16x2 lo (lo = residual)
__device__ __forceinline__ void split2(float x0, float x1, uint32_t& hi, uint32_t& lo) {
    uint32_t h;
    asm("cvt.rn.bf16x2.f32 %0, %1, %2;" : "=r"(h) : "f"(x1), "f"(x0));
    float h0 = __uint_as_float(h << 16);
    float h1 = __uint_as_float(h & 0xffff0000u);
    float l0 = x0 - h0, l1 = x1 - h1;
    asm("cvt.rn.bf16x2.f32 %0, %1, %2;" : "=r"(lo) : "f"(l1), "f"(l0));
    hi = h;
}
__device__ __forceinline__ void split8(const float4& v0, const float4& v1,
                                       uint4& hi, uint4& lo) {
    split2(v0.x, v0.y, hi.x, lo.x);
    split2(v0.z, v0.w, hi.y, lo.y);
    split2(v1.x, v1.y, hi.z, lo.z);
    split2(v1.z, v1.w, hi.w, lo.w);
}

// ---------------- split-bf16 GEMM via mma.sync ----------------
// C[M,N] = alpha * A[M,K] @ op(B), fp32 in/out.
// BNN=false: B is [N,K] row-major (NT). BNN=true: B is [K,N] row-major (NN).
// KLIM: kmax = rowStart + BM (causal K truncation).
template <bool CAUSAL, bool RELU, bool BNN, bool KLIM>
__global__ __launch_bounds__(NTHR)
void tc_gemm(const float* __restrict__ Aall, const float* __restrict__ Ball,
             float* __restrict__ Call,
             int K, int lda, int ldb, int ldc,
             int divA, int modA, size_t sA,
             int divB, int modB, size_t sB, size_t sC,
             const float* __restrict__ bias, const float* __restrict__ residual,
             float alpha)
{
    constexpr int B_TILE = BNN ? BNN_TILE : BNT_TILE;
    constexpr int BUFSZ  = 2 * A_TILE + 2 * B_TILE;

    extern __shared__ __align__(16) char smem[];
    const int tid = threadIdx.x;
    const int z = blockIdx.z;
    const float* A  = Aall + (size_t)((z / divA) % modA) * sA;
    const float* Bm = Ball + (size_t)((z / divB) % modB) * sB;
    float* C = Call + (size_t)z * sC;

    int by = blockIdx.y;
    if (CAUSAL || KLIM) by = gridDim.y - 1 - by;   // longest tiles first
    const int rowStart = by * BM;
    const int colStart = blockIdx.x * BN;
    if (CAUSAL && colStart > rowStart) return;

    const uint32_t sbase = (uint32_t)__cvta_generic_to_shared(smem);
    const int w = tid >> 5, lane = tid & 31;
    const int wm = (w >> 2) * 64;     // warp M offset (2 warps)
    const int wn = (w & 3) * 32;      // warp N offset (4 warps)

    const int kmax = KLIM ? (rowStart + BM) : K;
    const int nchunks = kmax / BK;

    float acc[4][4][4];
#pragma unroll
    for (int i = 0; i < 4; i++)
#pragma unroll
        for (int j = 0; j < 4; j++)
#pragma unroll
            for (int q = 0; q < 4; q++) acc[i][j][q] = 0.0f;

    // per-thread gmem/smem coordinates
    const int aRow = tid >> 2;            // unit u adds 64
    const int aCh  = tid & 3;
    const int bRowNT = tid >> 2;
    const int bChNT  = tid & 3;
    const int bRowNN = tid >> 4;          // unit u adds 16
    const int bChNN  = tid & 15;

    // ldmatrix base addresses (buffer 0)
    const uint32_t aLd = sbase + (uint32_t)((wm + (lane & 15)) * A_PITCH + (lane >> 4) * 16);
    const uint32_t bLdNT = sbase + 2 * A_TILE +
        (uint32_t)((wn + (lane & 15)) * BNT_PITCH + (lane >> 4) * 16);
    const uint32_t bLdNN = sbase + 2 * A_TILE +
        (uint32_t)(((lane & 7) + ((lane & 16) >> 1)) * BNN_PITCH +
                   ((wn >> 3) + ((lane >> 3) & 1)) * 16);

    float4 pA[2][2], pB[2][2];

    auto loadTiles = [&](int c) {
        const int k0 = c * BK;
#pragma unroll
        for (int u = 0; u < 2; u++) {
            const float* pa = A + (size_t)(rowStart + aRow + u * 64) * lda + k0 + aCh * 8;
            pA[u][0] = *reinterpret_cast<const float4*>(pa);
            pA[u][1] = *reinterpret_cast<const float4*>(pa + 4);
            if (!BNN) {
                const float* pb = Bm + (size_t)(colStart + bRowNT + u * 64) * ldb + k0 + bChNT * 8;
                pB[u][0] = *reinterpret_cast<const float4*>(pb);
                pB[u][1] = *reinterpret_cast<const float4*>(pb + 4);
            } else {
                const float* pb = Bm + (size_t)(k0 + bRowNN + u * 16) * ldb + colStart + bChNN * 8;
                pB[u][0] = *reinterpret_cast<const float4*>(pb);
                pB[u][1] = *reinterpret_cast<const float4*>(pb + 4);
            }
        }
    };
    auto storeTiles = [&](int buf) {
        char* base = smem + buf * BUFSZ;
#pragma unroll
        for (int u = 0; u < 2; u++) {
            uint4 hi, lo;
            split8(pA[u][0], pA[u][1], hi, lo);
            const int offA = (aRow + u * 64) * A_PITCH + aCh * 16;
            *reinterpret_cast<uint4*>(base + offA) = hi;
            *reinterpret_cast<uint4*>(base + A_TILE + offA) = lo;
            split8(pB[u][0], pB[u][1], hi, lo);
            if (!BNN) {
                const int offB = (bRowNT + u * 64) * BNT_PITCH + bChNT * 16;
                *reinterpret_cast<uint4*>(base + 2 * A_TILE + offB) = hi;
                *reinterpret_cast<uint4*>(base + 2 * A_TILE + B_TILE + offB) = lo;
            } else {
                const int offB = (bRowNN + u * 16) * BNN_PITCH + bChNN * 16;
                *reinterpret_cast<uint4*>(base + 2 * A_TILE + offB) = hi;
                *reinterpret_cast<uint4*>(base + 2 * A_TILE + B_TILE + offB) = lo;
            }
        }
    };

    loadTiles(0);
    storeTiles(0);
    __syncthreads();

    for (int c = 0; c < nchunks; c++) {
        const int buf = c & 1;
        const uint32_t bo = (uint32_t)(buf * BUFSZ);
        if (c + 1 < nchunks) loadTiles(c + 1);

#pragma unroll
        for (int ks = 0; ks < 2; ks++) {
            uint32_t aHi[4][4], aLo[4][4];
#pragma unroll
            for (int mi = 0; mi < 4; mi++) {
                ldsm_x4(aHi[mi], aLd + bo + (uint32_t)(mi * 16 * A_PITCH + ks * 32));
                ldsm_x4(aLo[mi], aLd + bo + (uint32_t)(A_TILE + mi * 16 * A_PITCH + ks * 32));
            }
            uint32_t bHi[2][4], bLo[2][4];
#pragma unroll
            for (int p = 0; p < 2; p++) {
                if (!BNN) {
                    ldsm_x4(bHi[p], bLdNT + bo + (uint32_t)(p * 16 * BNT_PITCH + ks * 32));
                    ldsm_x4(bLo[p], bLdNT + bo + (uint32_t)(B_TILE + p * 16 * BNT_PITCH + ks * 32));
                } else {
                    ldsm_x4_t(bHi[p], bLdNN + bo + (uint32_t)(p * 32 + ks * 16 * BNN_PITCH));
                    ldsm_x4_t(bLo[p], bLdNN + bo + (uint32_t)(B_TILE + p * 32 + ks * 16 * BNN_PITCH));
                }
            }
#pragma unroll
            for (int mi = 0; mi < 4; mi++)
#pragma unroll
                for (int ni = 0; ni < 4; ni++) {
                    const int p = ni >> 1, s = ni & 1;
                    mma16816(acc[mi][ni], aHi[mi], bHi[p][s], bHi[p][s + 2]);
                    mma16816(acc[mi][ni], aHi[mi], bLo[p][s], bLo[p][s + 2]);
                    mma16816(acc[mi][ni], aLo[mi], bHi[p][s], bHi[p][s + 2]);
                }
        }

        if (c + 1 < nchunks) storeTiles((c + 1) & 1);
        __syncthreads();
    }

    // ---------------- epilogue ----------------
    const int r0 = rowStart + wm + (lane >> 2);
    const int c0 = colStart + wn + (lane & 3) * 2;
#pragma unroll
    for (int mi = 0; mi < 4; mi++) {
        const int r = r0 + mi * 16;
#pragma unroll
        for (int ni = 0; ni < 4; ni++) {
            const int c = c0 + ni * 8;
            float v00 = acc[mi][ni][0] * alpha, v01 = acc[mi][ni][1] * alpha;
            float v10 = acc[mi][ni][2] * alpha, v11 = acc[mi][ni][3] * alpha;
            if (CAUSAL) {
                if (c > r)         v00 = 0.0f;
                if (c + 1 > r)     v01 = 0.0f;
                if (c > r + 8)     v10 = 0.0f;
                if (c + 1 > r + 8) v11 = 0.0f;
            }
            if (bias) {
                const float bv0 = bias[c], bv1 = bias[c + 1];
                v00 += bv0; v01 += bv1; v10 += bv0; v11 += bv1;
            }
            if (RELU) {
                v00 = fmaxf(v00, 0.0f); v01 = fmaxf(v01, 0.0f);
                v10 = fmaxf(v10, 0.0f); v11 = fmaxf(v11, 0.0f);
            }
            if (residual) {
                const float2 q0 = *reinterpret_cast<const float2*>(residual + (size_t)r * ldc + c);
                const float2 q1 = *reinterpret_cast<const float2*>(residual + (size_t)(r + 8) * ldc + c);
                v00 += q0.x; v01 += q0.y; v10 += q1.x; v11 += q1.y;
            }
            *reinterpret_cast<float2*>(C + (size_t)r * ldc + c)       = make_float2(v00, v01);
            *reinterpret_cast<float2*>(C + (size_t)(r + 8) * ldc + c) = make_float2(v10, v11);
        }
    }
}

// ---------------- fused head-mean + residual + LayerNorm ----------------
__global__ __launch_bounds__(128)
void ln_reduce(const float* __restrict__ Yp, const float* __restrict__ X,
               const float* __restrict__ gamma, const float* __restrict__ beta,
               float* __restrict__ Z)
{
    const int row = blockIdx.x;          // b*T + t
    const int b = row >> 11, t = row & (Tt - 1);
    const int tid = threadIdx.x;
    const int c0 = tid * 4;

    float4 acc = make_float4(0.f, 0.f, 0.f, 0.f);
#pragma unroll
    for (int h = 0; h < Hh; h++) {
        const float4 y4 = *reinterpret_cast<const float4*>(
            Yp + ((size_t)(b * Hh + h) * Tt + t) * Dd + c0);
        acc.x += y4.x; acc.y += y4.y; acc.z += y4.z; acc.w += y4.w;
    }
    const float4 x4 = *reinterpret_cast<const float4*>(X + (size_t)row * Dd + c0);
    float v[4] = { acc.x * 0.125f + x4.x, acc.y * 0.125f + x4.y,
                   acc.z * 0.125f + x4.z, acc.w * 0.125f + x4.w };

    float s  = v[0] + v[1] + v[2] + v[3];
    float sq = v[0]*v[0] + v[1]*v[1] + v[2]*v[2] + v[3]*v[3];
#pragma unroll
    for (int o = 16; o > 0; o >>= 1) {
        s  += __shfl_xor_sync(0xffffffffu, s, o);
        sq += __shfl_xor_sync(0xffffffffu, sq, o);
    }
    __shared__ float sh[8];
    __shared__ float s_mean, s_rstd;
    const int wq = tid >> 5, lane = tid & 31;
    if (lane == 0) { sh[wq] = s; sh[4 + wq] = sq; }
    __syncthreads();
    if (tid == 0) {
        float ts = sh[0] + sh[1] + sh[2] + sh[3];
        float tq = sh[4] + sh[5] + sh[6] + sh[7];
        float mean = ts / (float)Dd;
        float var  = tq / (float)Dd - mean * mean;
        s_mean = mean; s_rstd = rsqrtf(var + 1e-5f);
    }
    __syncthreads();
    const float mean = s_mean, rstd = s_rstd;
#pragma unroll
    for (int i = 0; i < 4; i++) {
        const int c = c0 + i;
        Z[(size_t)row * Dd + c] = (v[i] - mean) * rstd * gamma[c] + beta[c];
    }
}

// ---------------- launcher ----------------
extern "C" void kernel_launch(void* const* d_in, const int* in_sizes, int n_in,
                              void* d_out, int out_size)
{
    (void)in_sizes; (void)n_in; (void)out_size;
    const float* x     = (const float*)d_in[0];
    const float* P     = (const float*)d_in[1];
    const float* Q     = (const float*)d_in[2];
    const float* gamma = (const float*)d_in[3];
    const float* beta  = (const float*)d_in[4];
    const float* W1    = (const float*)d_in[5];
    const float* b1    = (const float*)d_in[6];
    const float* W2    = (const float*)d_in[7];
    const float* b2    = (const float*)d_in[8];
    const float* Wp    = (const float*)d_in[9];
    const float* bp    = (const float*)d_in[10];
    float* out = (float*)d_out;

    float *QZ, *PZ, *S, *Yp, *Z, *M1, *Z2;
    cudaGetSymbolAddress((void**)&QZ, g_QZ);
    cudaGetSymbolAddress((void**)&PZ, g_PZ);
    cudaGetSymbolAddress((void**)&S,  g_S);
    cudaGetSymbolAddress((void**)&Yp, g_Yp);
    cudaGetSymbolAddress((void**)&Z,  g_Z);
    cudaGetSymbolAddress((void**)&M1, g_M1);
    cudaGetSymbolAddress((void**)&Z2, g_Z2);

    constexpr int SM_NT = 2 * (2 * A_TILE + 2 * BNT_TILE);   // 81920
    constexpr int SM_NN = 2 * (2 * A_TILE + 2 * BNN_TILE);   // 75776

    static bool attr_done = false;
    if (!attr_done) {
        cudaFuncSetAttribute(tc_gemm<false,false,false,false>,
                             cudaFuncAttributeMaxDynamicSharedMemorySize, SM_NT);
        cudaFuncSetAttribute(tc_gemm<true,false,false,false>,
                             cudaFuncAttributeMaxDynamicSharedMemorySize, SM_NT);
        cudaFuncSetAttribute(tc_gemm<false,false,true,true>,
                             cudaFuncAttributeMaxDynamicSharedMemorySize, SM_NN);
        cudaFuncSetAttribute(tc_gemm<false,true,false,false>,
                             cudaFuncAttributeMaxDynamicSharedMemorySize, SM_NT);
        attr_done = true;
    }

    const dim3 blk(NTHR);
    const float inv_sqrt_d = 1.0f / sqrtf((float)Dd);

    // 1) QZ[z=b*8+h] = x[b] @ Q[h]^T   [T x D]
    tc_gemm<false,false,false,false><<<dim3(4, 16, 16), blk, SM_NT>>>(
        x, Q, QZ, Dd, Dd, Dd, Dd,
        Hh, Bb, (size_t)Tt * Dd,
        1,  Hh, (size_t)Dd * Dd,
        (size_t)Tt * Dd, nullptr, nullptr, 1.0f);

    // 2) PZ[z] = x[b] @ P[h]^T   [T x D]
    tc_gemm<false,false,false,false><<<dim3(4, 16, 16), blk, SM_NT>>>(
        x, P, PZ, Dd, Dd, Dd, Dd,
        Hh, Bb, (size_t)Tt * Dd,
        1,  Hh, (size_t)Dd * Dd,
        (size_t)Tt * Dd, nullptr, nullptr, 1.0f);

    // 3) S[z] = tril(QZ[z] @ x[b]^T) / sqrt(D)   [T x T]
    tc_gemm<true,false,false,false><<<dim3(16, 16, 16), blk, SM_NT>>>(
        QZ, x, S, Dd, Dd, Dd, Tt,
        1, Bb * Hh, (size_t)Tt * Dd,
        Hh, Bb,     (size_t)Tt * Dd,
        (size_t)Tt * Tt, nullptr, nullptr, inv_sqrt_d);

    // 4) Yp[z] = S[z] @ PZ[z]   [T x D], NN, causal K-limit
    tc_gemm<false,false,true,true><<<dim3(4, 16, 16), blk, SM_NN>>>(
        S, PZ, Yp, Tt, Tt, Dd, Dd,
        1, Bb * Hh, (size_t)Tt * Tt,
        1, Bb * Hh, (size_t)Tt * Dd,
        (size_t)Tt * Dd, nullptr, nullptr, 1.0f);

    // 5) Z = LayerNorm(mean_h(Yp) + x)
    ln_reduce<<<Bb * Tt, 128>>>(Yp, x, gamma, beta, Z);

    // 6) M1 = relu(Z @ W1^T + b1)   [4096 x 1024]
    tc_gemm<false,true,false,false><<<dim3(8, 32, 1), blk, SM_NT>>>(
        Z, W1, M1, Dd, Dd, Dd, 2 * Dd,
        1, 1, 0, 1, 1, 0, 0, b1, nullptr, 1.0f);

    // 7) Z2 = Z + (M1 @ W2^T + b2)  [4096 x 512]
    tc_gemm<false,false,false,false><<<dim3(4, 32, 1), blk, SM_NT>>>(
        M1, W2, Z2, 2 * Dd, 2 * Dd, 2 * Dd, Dd,
        1, 1, 0, 1, 1, 0, 0, b2, Z, 1.0f);

    // 8) out = Z2 @ Wp^T + bp       [4096 x 512]
    tc_gemm<false,false,false,false><<<dim3(4, 32, 1), blk, SM_NT>>>(
        Z2, Wp, out, Dd, Dd, Dd, Dd,
        1, 1, 0, 1, 1, 0, 0, bp, nullptr, 1.0f);
}

// round 4
// speedup vs baseline: 5.0897x; 1.4474x over previous
#include <cuda_runtime.h>
#include <cuda_fp16.h>
#include <stdint.h>
#include <math.h>

#define Bb 2
#define Tt 2048
#define Dd 512
#define Hh 8

// ---------------- scratch (device globals) ----------------
__device__ __align__(16) float g_QZ [(size_t)Bb*Hh*Tt*Dd];   // 64 MB
__device__ __align__(16) float g_PZ [(size_t)Bb*Hh*Tt*Dd];   // 64 MB
__device__ __align__(16) float g_S  [(size_t)Bb*Hh*Tt*Tt];   // 256 MB
__device__ __align__(16) float g_Yp [(size_t)Bb*Hh*Tt*Dd];   // 64 MB
__device__ __align__(16) float g_Z  [(size_t)Bb*Tt*Dd];      // 8 MB
__device__ __align__(16) float g_M1 [(size_t)Bb*Tt*2*Dd];    // 16 MB
__device__ __align__(16) float g_Z2 [(size_t)Bb*Tt*Dd];      // 8 MB

constexpr int BM = 128, BN = 128, BK = 32, NTHR = 512;

// smem tile geometry
constexpr int A_PITCH = 80;                 // 4x16B chunks + 16B pad: ldmatrix conflict-free
constexpr int A_TILE  = BM * A_PITCH;       // 10240 B (f16 128x32), x2 for hi+lo
constexpr int BNT_PITCH = 80;
constexpr int BNT_TILE  = BN * BNT_PITCH;   // 10240 (single precision-level B)
constexpr int BNN_PITCH = 272;              // 16x16B chunks + 16B pad
constexpr int BNN_TILE  = BK * BNN_PITCH;   // 8704

// ---------------- PTX helpers ----------------
__device__ __forceinline__ void ldsm_x4(uint32_t (&r)[4], uint32_t addr) {
    asm volatile("ldmatrix.sync.aligned.m8n8.x4.shared.b16 {%0,%1,%2,%3}, [%4];"
                 : "=r"(r[0]), "=r"(r[1]), "=r"(r[2]), "=r"(r[3]) : "r"(addr));
}
__device__ __forceinline__ void ldsm_x4_t(uint32_t (&r)[4], uint32_t addr) {
    asm volatile("ldmatrix.sync.aligned.m8n8.x4.trans.shared.b16 {%0,%1,%2,%3}, [%4];"
                 : "=r"(r[0]), "=r"(r[1]), "=r"(r[2]), "=r"(r[3]) : "r"(addr));
}
__device__ __forceinline__ void mma16816(float (&d)[4], const uint32_t (&a)[4],
                                         uint32_t b0, uint32_t b1) {
    asm volatile("mma.sync.aligned.m16n8k16.row.col.f32.f16.f16.f32 "
                 "{%0,%1,%2,%3}, {%4,%5,%6,%7}, {%8,%9}, {%0,%1,%2,%3};"
                 : "+f"(d[0]), "+f"(d[1]), "+f"(d[2]), "+f"(d[3])
                 : "r"(a[0]), "r"(a[1]), "r"(a[2]), "r"(a[3]), "r"(b0), "r"(b1));
}

// fp32 pair -> packed f16x2 hi + f16x2 lo (lo = rounding residual)
__device__ __forceinline__ void split2h(float x0, float x1, uint32_t& hi, uint32_t& lo) {
    __half2 h = __float22half2_rn(make_float2(x0, x1));
    float2 hf = __half22float2(h);
    __half2 l = __float22half2_rn(make_float2(x0 - hf.x, x1 - hf.y));
    hi = *reinterpret_cast<uint32_t*>(&h);
    lo = *reinterpret_cast<uint32_t*>(&l);
}
__device__ __forceinline__ uint32_t pack2h(float x0, float x1) {
    __half2 h = __float22half2_rn(make_float2(x0, x1));
    return *reinterpret_cast<uint32_t*>(&h);
}
__device__ __forceinline__ void split8h(const float4& v0, const float4& v1,
                                        uint4& hi, uint4& lo) {
    split2h(v0.x, v0.y, hi.x, lo.x);
    split2h(v0.z, v0.w, hi.y, lo.y);
    split2h(v1.x, v1.y, hi.z, lo.z);
    split2h(v1.z, v1.w, hi.w, lo.w);
}
__device__ __forceinline__ uint4 pack8h(const float4& v0, const float4& v1) {
    uint4 r;
    r.x = pack2h(v0.x, v0.y); r.y = pack2h(v0.z, v0.w);
    r.z = pack2h(v1.x, v1.y); r.w = pack2h(v1.z, v1.w);
    return r;
}

// ---------------- asymmetric-split f16 GEMM via mma.sync ----------------
// C[M,N] = alpha * A[M,K] @ op(B); A split into hi+lo f16 (2 MMAs), B single f16.
// BNN=false: B is [N,K] row-major (NT). BNN=true: B is [K,N] row-major (NN).
// KLIM: kmax = rowStart + BM (causal K truncation).
template <bool CAUSAL, bool RELU, bool BNN, bool KLIM>
__global__ __launch_bounds__(NTHR, 1)
void tc_gemm(const float* __restrict__ Aall, const float* __restrict__ Ball,
             float* __restrict__ Call,
             int K, int lda, int ldb, int ldc,
             int divA, int modA, size_t sA,
             int divB, int modB, size_t sB, size_t sC,
             const float* __restrict__ bias, const float* __restrict__ residual,
             float alpha)
{
    constexpr int B_TILE = BNN ? BNN_TILE : BNT_TILE;
    constexpr int BBASE  = 2 * A_TILE;
    constexpr int BUFSZ  = 2 * A_TILE + B_TILE;

    extern __shared__ __align__(16) char smem[];
    const int tid = threadIdx.x;
    const int z = blockIdx.z;
    const float* A  = Aall + (size_t)((z / divA) % modA) * sA;
    const float* Bm = Ball + (size_t)((z / divB) % modB) * sB;
    float* C = Call + (size_t)z * sC;

    int by = blockIdx.y;
    if (CAUSAL || KLIM) by = gridDim.y - 1 - by;   // longest tiles first
    const int rowStart = by * BM;
    const int colStart = blockIdx.x * BN;
    if (CAUSAL && colStart > rowStart) return;

    const uint32_t sbase = (uint32_t)__cvta_generic_to_shared(smem);
    const int w = tid >> 5, lane = tid & 31;
    const int wm = (w & 3) * 32;      // warp M offset (4 warps)
    const int wn = (w >> 2) * 32;     // warp N offset (4 warps)

    const int kmax = KLIM ? (rowStart + BM) : K;
    const int nchunks = kmax / BK;

    float acc[2][4][4];
#pragma unroll
    for (int i = 0; i < 2; i++)
#pragma unroll
        for (int j = 0; j < 4; j++)
#pragma unroll
            for (int q = 0; q < 4; q++) acc[i][j][q] = 0.0f;

    // per-thread staging coordinates (512 threads)
    const int aRow = tid >> 2;          // 0..127
    const int aCh  = tid & 3;           // 0..3
    const int bRowNN = tid >> 4;        // 0..31
    const int bChNN  = tid & 15;        // 0..15

    // incremented gmem pointers
    const float* paCur = A + (size_t)(rowStart + aRow) * lda + aCh * 8;
    const float* pbCur = BNN
        ? Bm + (size_t)bRowNN * ldb + colStart + bChNN * 8
        : Bm + (size_t)(colStart + aRow) * ldb + aCh * 8;
    const int pbStep = BNN ? BK * ldb : BK;

    // smem staging offsets
    const int offA = aRow * A_PITCH + aCh * 16;
    const int offB = BNN ? (bRowNN * BNN_PITCH + bChNN * 16)
                         : (aRow * BNT_PITCH + aCh * 16);

    // ldmatrix base addresses (buffer 0)
    const uint32_t aLd = sbase + (uint32_t)((wm + (lane & 15)) * A_PITCH + (lane >> 4) * 16);
    const uint32_t bLdNT = sbase + BBASE +
        (uint32_t)((wn + (lane & 15)) * BNT_PITCH + (lane >> 4) * 16);
    const uint32_t bLdNN = sbase + BBASE +
        (uint32_t)(((lane & 7) + ((lane & 16) >> 1)) * BNN_PITCH +
                   ((wn >> 3) + ((lane >> 3) & 1)) * 16);

    float4 pA0, pA1, pB0, pB1;

    auto loadTiles = [&]() {
        pA0 = *reinterpret_cast<const float4*>(paCur);
        pA1 = *reinterpret_cast<const float4*>(paCur + 4);
        pB0 = *reinterpret_cast<const float4*>(pbCur);
        pB1 = *reinterpret_cast<const float4*>(pbCur + 4);
        paCur += BK;
        pbCur += pbStep;
    };
    auto storeTiles = [&](int buf) {
        char* base = smem + buf * BUFSZ;
        uint4 hi, lo;
        split8h(pA0, pA1, hi, lo);
        *reinterpret_cast<uint4*>(base + offA) = hi;
        *reinterpret_cast<uint4*>(base + A_TILE + offA) = lo;
        *reinterpret_cast<uint4*>(base + BBASE + offB) = pack8h(pB0, pB1);
    };

    loadTiles();
    storeTiles(0);
    __syncthreads();

    for (int c = 0; c < nchunks; c++) {
        const uint32_t bo = (uint32_t)((c & 1) * BUFSZ);
        if (c + 1 < nchunks) loadTiles();

#pragma unroll
        for (int ks = 0; ks < 2; ks++) {
            uint32_t aHi[2][4], aLo[2][4], bF[2][4];
#pragma unroll
            for (int mi = 0; mi < 2; mi++) {
                ldsm_x4(aHi[mi], aLd + bo + (uint32_t)(mi * 16 * A_PITCH + ks * 32));
                ldsm_x4(aLo[mi], aLd + bo + (uint32_t)(A_TILE + mi * 16 * A_PITCH + ks * 32));
            }
#pragma unroll
            for (int p = 0; p < 2; p++) {
                if (!BNN)
                    ldsm_x4(bF[p], bLdNT + bo + (uint32_t)(p * 16 * BNT_PITCH + ks * 32));
                else
                    ldsm_x4_t(bF[p], bLdNN + bo + (uint32_t)(p * 32 + ks * 16 * BNN_PITCH));
            }
#pragma unroll
            for (int mi = 0; mi < 2; mi++)
#pragma unroll
                for (int ni = 0; ni < 4; ni++) {
                    const int p = ni >> 1, s = ni & 1;
                    mma16816(acc[mi][ni], aHi[mi], bF[p][s], bF[p][s + 2]);
                    mma16816(acc[mi][ni], aLo[mi], bF[p][s], bF[p][s + 2]);
                }
        }

        if (c + 1 < nchunks) storeTiles((c + 1) & 1);
        __syncthreads();
    }

    // ---------------- epilogue ----------------
    const int r0 = rowStart + wm + (lane >> 2);
    const int c0 = colStart + wn + (lane & 3) * 2;
#pragma unroll
    for (int mi = 0; mi < 2; mi++) {
        const int r = r0 + mi * 16;
#pragma unroll
        for (int ni = 0; ni < 4; ni++) {
            const int c = c0 + ni * 8;
            float v00 = acc[mi][ni][0] * alpha, v01 = acc[mi][ni][1] * alpha;
            float v10 = acc[mi][ni][2] * alpha, v11 = acc[mi][ni][3] * alpha;
            if (CAUSAL) {
                if (c > r)         v00 = 0.0f;
                if (c + 1 > r)     v01 = 0.0f;
                if (c > r + 8)     v10 = 0.0f;
                if (c + 1 > r + 8) v11 = 0.0f;
            }
            if (bias) {
                const float bv0 = bias[c], bv1 = bias[c + 1];
                v00 += bv0; v01 += bv1; v10 += bv0; v11 += bv1;
            }
            if (RELU) {
                v00 = fmaxf(v00, 0.0f); v01 = fmaxf(v01, 0.0f);
                v10 = fmaxf(v10, 0.0f); v11 = fmaxf(v11, 0.0f);
            }
            if (residual) {
                const float2 q0 = *reinterpret_cast<const float2*>(residual + (size_t)r * ldc + c);
                const float2 q1 = *reinterpret_cast<const float2*>(residual + (size_t)(r + 8) * ldc + c);
                v00 += q0.x; v01 += q0.y; v10 += q1.x; v11 += q1.y;
            }
            *reinterpret_cast<float2*>(C + (size_t)r * ldc + c)       = make_float2(v00, v01);
            *reinterpret_cast<float2*>(C + (size_t)(r + 8) * ldc + c) = make_float2(v10, v11);
        }
    }
}

// ---------------- fused head-mean + residual + LayerNorm ----------------
__global__ __launch_bounds__(128)
void ln_reduce(const float* __restrict__ Yp, const float* __restrict__ X,
               const float* __restrict__ gamma, const float* __restrict__ beta,
               float* __restrict__ Z)
{
    const int row = blockIdx.x;          // b*T + t
    const int b = row >> 11, t = row & (Tt - 1);
    const int tid = threadIdx.x;
    const int c0 = tid * 4;

    float4 acc = make_float4(0.f, 0.f, 0.f, 0.f);
#pragma unroll
    for (int h = 0; h < Hh; h++) {
        const float4 y4 = *reinterpret_cast<const float4*>(
            Yp + ((size_t)(b * Hh + h) * Tt + t) * Dd + c0);
        acc.x += y4.x; acc.y += y4.y; acc.z += y4.z; acc.w += y4.w;
    }
    const float4 x4 = *reinterpret_cast<const float4*>(X + (size_t)row * Dd + c0);
    float v[4] = { acc.x * 0.125f + x4.x, acc.y * 0.125f + x4.y,
                   acc.z * 0.125f + x4.z, acc.w * 0.125f + x4.w };

    float s  = v[0] + v[1] + v[2] + v[3];
    float sq = v[0]*v[0] + v[1]*v[1] + v[2]*v[2] + v[3]*v[3];
#pragma unroll
    for (int o = 16; o > 0; o >>= 1) {
        s  += __shfl_xor_sync(0xffffffffu, s, o);
        sq += __shfl_xor_sync(0xffffffffu, sq, o);
    }
    __shared__ float sh[8];
    __shared__ float s_mean, s_rstd;
    const int wq = tid >> 5, lane = tid & 31;
    if (lane == 0) { sh[wq] = s; sh[4 + wq] = sq; }
    __syncthreads();
    if (tid == 0) {
        float ts = sh[0] + sh[1] + sh[2] + sh[3];
        float tq = sh[4] + sh[5] + sh[6] + sh[7];
        float mean = ts / (float)Dd;
        float var  = tq / (float)Dd - mean * mean;
        s_mean = mean; s_rstd = rsqrtf(var + 1e-5f);
    }
    __syncthreads();
    const float mean = s_mean, rstd = s_rstd;
#pragma unroll
    for (int i = 0; i < 4; i++) {
        const int c = c0 + i;
        Z[(size_t)row * Dd + c] = (v[i] - mean) * rstd * gamma[c] + beta[c];
    }
}

// ---------------- launcher ----------------
extern "C" void kernel_launch(void* const* d_in, const int* in_sizes, int n_in,
                              void* d_out, int out_size)
{
    (void)in_sizes; (void)n_in; (void)out_size;
    const float* x     = (const float*)d_in[0];
    const float* P     = (const float*)d_in[1];
    const float* Q     = (const float*)d_in[2];
    const float* gamma = (const float*)d_in[3];
    const float* beta  = (const float*)d_in[4];
    const float* W1    = (const float*)d_in[5];
    const float* b1    = (const float*)d_in[6];
    const float* W2    = (const float*)d_in[7];
    const float* b2    = (const float*)d_in[8];
    const float* Wp    = (const float*)d_in[9];
    const float* bp    = (const float*)d_in[10];
    float* out = (float*)d_out;

    float *QZ, *PZ, *S, *Yp, *Z, *M1, *Z2;
    cudaGetSymbolAddress((void**)&QZ, g_QZ);
    cudaGetSymbolAddress((void**)&PZ, g_PZ);
    cudaGetSymbolAddress((void**)&S,  g_S);
    cudaGetSymbolAddress((void**)&Yp, g_Yp);
    cudaGetSymbolAddress((void**)&Z,  g_Z);
    cudaGetSymbolAddress((void**)&M1, g_M1);
    cudaGetSymbolAddress((void**)&Z2, g_Z2);

    constexpr int SM_NT = 2 * (2 * A_TILE + BNT_TILE);   // 61440
    constexpr int SM_NN = 2 * (2 * A_TILE + BNN_TILE);   // 58368

    static bool attr_done = false;
    if (!attr_done) {
        cudaFuncSetAttribute(tc_gemm<false,false,false,false>,
                             cudaFuncAttributeMaxDynamicSharedMemorySize, SM_NT);
        cudaFuncSetAttribute(tc_gemm<true,false,false,false>,
                             cudaFuncAttributeMaxDynamicSharedMemorySize, SM_NT);
        cudaFuncSetAttribute(tc_gemm<false,false,true,true>,
                             cudaFuncAttributeMaxDynamicSharedMemorySize, SM_NN);
        cudaFuncSetAttribute(tc_gemm<false,true,false,false>,
                             cudaFuncAttributeMaxDynamicSharedMemorySize, SM_NT);
        attr_done = true;
    }

    const dim3 blk(NTHR);
    const float inv_sqrt_d = 1.0f / sqrtf((float)Dd);

    // 1) QZ[z=b*8+h] = x[b] @ Q[h]^T   [T x D]
    tc_gemm<false,false,false,false><<<dim3(4, 16, 16), blk, SM_NT>>>(
        x, Q, QZ, Dd, Dd, Dd, Dd,
        Hh, Bb, (size_t)Tt * Dd,
        1,  Hh, (size_t)Dd * Dd,
        (size_t)Tt * Dd, nullptr, nullptr, 1.0f);

    // 2) PZ[z] = x[b] @ P[h]^T   [T x D]
    tc_gemm<false,false,false,false><<<dim3(4, 16, 16), blk, SM_NT>>>(
        x, P, PZ, Dd, Dd, Dd, Dd,
        Hh, Bb, (size_t)Tt * Dd,
        1,  Hh, (size_t)Dd * Dd,
        (size_t)Tt * Dd, nullptr, nullptr, 1.0f);

    // 3) S[z] = tril(QZ[z] @ x[b]^T) / sqrt(D)   [T x T]
    tc_gemm<true,false,false,false><<<dim3(16, 16, 16), blk, SM_NT>>>(
        QZ, x, S, Dd, Dd, Dd, Tt,
        1, Bb * Hh, (size_t)Tt * Dd,
        Hh, Bb,     (size_t)Tt * Dd,
        (size_t)Tt * Tt, nullptr, nullptr, inv_sqrt_d);

    // 4) Yp[z] = S[z] @ PZ[z]   [T x D], NN, causal K-limit
    tc_gemm<false,false,true,true><<<dim3(4, 16, 16), blk, SM_NN>>>(
        S, PZ, Yp, Tt, Tt, Dd, Dd,
        1, Bb * Hh, (size_t)Tt * Tt,
        1, Bb * Hh, (size_t)Tt * Dd,
        (size_t)Tt * Dd, nullptr, nullptr, 1.0f);

    // 5) Z = LayerNorm(mean_h(Yp) + x)
    ln_reduce<<<Bb * Tt, 128>>>(Yp, x, gamma, beta, Z);

    // 6) M1 = relu(Z @ W1^T + b1)   [4096 x 1024]
    tc_gemm<false,true,false,false><<<dim3(8, 32, 1), blk, SM_NT>>>(
        Z, W1, M1, Dd, Dd, Dd, 2 * Dd,
        1, 1, 0, 1, 1, 0, 0, b1, nullptr, 1.0f);

    // 7) Z2 = Z + (M1 @ W2^T + b2)  [4096 x 512]
    tc_gemm<false,false,false,false><<<dim3(4, 32, 1), blk, SM_NT>>>(
        M1, W2, Z2, 2 * Dd, 2 * Dd, 2 * Dd, Dd,
        1, 1, 0, 1, 1, 0, 0, b2, Z, 1.0f);

    // 8) out = Z2 @ Wp^T + bp       [4096 x 512]
    tc_gemm<false,false,false,false><<<dim3(4, 32, 1), blk, SM_NT>>>(
        Z2, Wp, out, Dd, Dd, Dd, Dd,
        1, 1, 0, 1, 1, 0, 0, bp, nullptr, 1.0f);
}